// round 4
// baseline (speedup 1.0000x reference)
#include <cuda_runtime.h>
#include <math.h>

#define T_TOK 8192
#define HD    2048
#define NE    8
#define ID    1408
#define TWO_I 2816
#define NA    16384
#define NA_PAD 17408   // 16384 + 8*128: per-expert regions aligned to 128 rows
#define MAX_TILES 144

// ---------------- scratch (device globals; no allocation allowed) ----------------
__device__ float g_xin[(size_t)NA_PAD * HD];     // gathered, routing-weight-scaled inputs
__device__ float g_hidden[(size_t)NA_PAD * ID];  // routed swiglu activations
__device__ float g_shidden[(size_t)T_TOK * ID];  // shared-expert swiglu activations
__device__ int   g_top_e[NA];
__device__ float g_top_p[NA];
__device__ float g_gate[T_TOK];
__device__ int   g_cnt[NE], g_off[NE], g_fill[NE];
__device__ int   g_row_token[NA_PAD];
__device__ int   g_tile_e[MAX_TILES], g_tile_row0[MAX_TILES], g_tile_rows[MAX_TILES];
__device__ int   g_ntiles;

// ---------------- helpers ----------------
__device__ __forceinline__ float to_tf32(float f) {
    unsigned u;
    asm("cvt.rna.tf32.f32 %0, %1;" : "=r"(u) : "f"(f));
    return __uint_as_float(u);
}

__device__ __forceinline__ void mma_tf32(float* c, const float* a, float b0, float b1) {
    asm volatile(
        "mma.sync.aligned.m16n8k8.row.col.f32.tf32.tf32.f32 "
        "{%0,%1,%2,%3}, {%4,%5,%6,%7}, {%8,%9}, {%0,%1,%2,%3};\n"
        : "+f"(c[0]), "+f"(c[1]), "+f"(c[2]), "+f"(c[3])
        : "r"(__float_as_uint(a[0])), "r"(__float_as_uint(a[1])),
          "r"(__float_as_uint(a[2])), "r"(__float_as_uint(a[3])),
          "r"(__float_as_uint(b0)),  "r"(__float_as_uint(b1)));
}

// ---------------- small kernels ----------------
__global__ void init_kernel() {
    int t = threadIdx.x;
    if (t < NE) { g_cnt[t] = 0; g_fill[t] = 0; }
}

// one warp per token: router logits, top-2 softmax, shared sigmoid gate
__global__ void router_kernel(const float* __restrict__ x,
                              const float* __restrict__ wr,
                              const float* __restrict__ wsg) {
    int gw   = (blockIdx.x * blockDim.x + threadIdx.x) >> 5;
    int lane = threadIdx.x & 31;
    if (gw >= T_TOK) return;
    const float* xr = x + (size_t)gw * HD;
    float acc[NE];
#pragma unroll
    for (int e = 0; e < NE; e++) acc[e] = 0.f;
    float ag = 0.f;
    for (int h = lane; h < HD; h += 32) {
        float xv = xr[h];
        const float4* w = (const float4*)(wr + (size_t)h * NE);
        float4 w0 = w[0], w1 = w[1];
        acc[0] += xv * w0.x; acc[1] += xv * w0.y; acc[2] += xv * w0.z; acc[3] += xv * w0.w;
        acc[4] += xv * w1.x; acc[5] += xv * w1.y; acc[6] += xv * w1.z; acc[7] += xv * w1.w;
        ag += xv * wsg[h];
    }
#pragma unroll
    for (int o = 16; o > 0; o >>= 1) {
#pragma unroll
        for (int e = 0; e < NE; e++) acc[e] += __shfl_xor_sync(0xffffffffu, acc[e], o);
        ag += __shfl_xor_sync(0xffffffffu, ag, o);
    }
    if (lane == 0) {
        int i0 = 0; float v0 = acc[0];
#pragma unroll
        for (int e = 1; e < NE; e++) if (acc[e] > v0) { v0 = acc[e]; i0 = e; }
        int i1 = -1; float v1 = -1e30f;
#pragma unroll
        for (int e = 0; e < NE; e++) if (e != i0 && acc[e] > v1) { v1 = acc[e]; i1 = e; }
        float t  = __expf(v1 - v0);
        float p0 = 1.f / (1.f + t);
        float p1 = t  / (1.f + t);
        g_top_e[gw * 2]     = i0;
        g_top_e[gw * 2 + 1] = i1;
        g_top_p[gw * 2]     = p0;
        g_top_p[gw * 2 + 1] = p1;
        atomicAdd(&g_cnt[i0], 1);
        atomicAdd(&g_cnt[i1], 1);
        g_gate[gw] = 1.f / (1.f + __expf(-ag));
    }
}

// Expert regions aligned UP to 128 rows so no GEMM tile straddles two experts.
// This removes the g_hidden write race between adjacent experts' edge tiles.
__global__ void scan_kernel() {
    if (threadIdx.x == 0 && blockIdx.x == 0) {
        int off = 0, nt = 0;
        for (int e = 0; e < NE; e++) {
            g_off[e] = off;
            int c = g_cnt[e];
            for (int r = 0; r < c; r += 128) {
                g_tile_e[nt]    = e;
                g_tile_row0[nt] = off + r;
                g_tile_rows[nt] = (c - r < 128) ? (c - r) : 128;
                nt++;
            }
            off = (off + c + 127) & ~127;   // 128-align next expert's region
        }
        g_ntiles = nt;
    }
}

// one block per assignment: copy x[t]*p into the expert-grouped buffer
__global__ void scatter_kernel(const float* __restrict__ x) {
    int a = blockIdx.x;
    int t = a >> 1;
    __shared__ int srow;
    int   e = g_top_e[a];
    float p = g_top_p[a];
    if (threadIdx.x == 0) {
        int pos = atomicAdd(&g_fill[e], 1);
        int row = g_off[e] + pos;
        g_row_token[row] = t;
        srow = row;
    }
    __syncthreads();
    int row = srow;
    const float4* src = (const float4*)(x + (size_t)t * HD);
    float4*       dst = (float4*)(g_xin + (size_t)row * HD);
    for (int i = threadIdx.x; i < HD / 4; i += blockDim.x) {
        float4 v = src[i];
        v.x *= p; v.y *= p; v.z *= p; v.w *= p;
        dst[i] = v;
    }
}

// ---------------- GEMM1: X @ W_gate_up, fused SwiGLU ----------------
// BM=128, dual BN=64 (g and u columns), BK=16, 256 threads (warps 4x2)
template <bool SHARED>
__global__ __launch_bounds__(256) void gemm1_kernel(const float* __restrict__ xglob,
                                                    const float* __restrict__ wgu) {
    int tile = blockIdx.x;
    int row0;
    const float* B;
    if (SHARED) {
        row0 = tile * 128;
        B = wgu;
    } else {
        if (tile >= g_ntiles) return;
        row0 = g_tile_row0[tile];
        B = wgu + (size_t)g_tile_e[tile] * HD * TWO_I;
    }
    const float* A = SHARED ? xglob : g_xin;
    int col0 = blockIdx.y * 64;

    __shared__ float As[128][18];
    __shared__ float Bg[64][18];
    __shared__ float Bu[64][18];

    int tid = threadIdx.x, lane = tid & 31, warp = tid >> 5;
    int wm = warp >> 1, wn = warp & 1;

    float cg[2][4][4], cu[2][4][4];
#pragma unroll
    for (int i = 0; i < 2; i++)
#pragma unroll
        for (int j = 0; j < 4; j++)
#pragma unroll
            for (int q = 0; q < 4; q++) { cg[i][j][q] = 0.f; cu[i][j][q] = 0.f; }

    int ar = tid >> 1, ac = (tid & 1) * 8;
    int bk = tid >> 4, bn = (tid & 15) * 4;

    for (int k0 = 0; k0 < HD; k0 += 16) {
        const float* asrc = A + (size_t)(row0 + ar) * HD + k0 + ac;
        float4 a0 = *(const float4*)asrc;
        float4 a1 = *(const float4*)(asrc + 4);
        As[ar][ac + 0] = to_tf32(a0.x); As[ar][ac + 1] = to_tf32(a0.y);
        As[ar][ac + 2] = to_tf32(a0.z); As[ar][ac + 3] = to_tf32(a0.w);
        As[ar][ac + 4] = to_tf32(a1.x); As[ar][ac + 5] = to_tf32(a1.y);
        As[ar][ac + 6] = to_tf32(a1.z); As[ar][ac + 7] = to_tf32(a1.w);

        const float* bsrc = B + (size_t)(k0 + bk) * TWO_I + col0 + bn;
        float4 vg = *(const float4*)bsrc;
        float4 vu = *(const float4*)(bsrc + ID);
        Bg[bn + 0][bk] = to_tf32(vg.x); Bg[bn + 1][bk] = to_tf32(vg.y);
        Bg[bn + 2][bk] = to_tf32(vg.z); Bg[bn + 3][bk] = to_tf32(vg.w);
        Bu[bn + 0][bk] = to_tf32(vu.x); Bu[bn + 1][bk] = to_tf32(vu.y);
        Bu[bn + 2][bk] = to_tf32(vu.z); Bu[bn + 3][bk] = to_tf32(vu.w);
        __syncthreads();

#pragma unroll
        for (int ks = 0; ks < 2; ks++) {
            int kb = ks * 8;
            float a[2][4];
#pragma unroll
            for (int mt = 0; mt < 2; mt++) {
                int r = wm * 32 + mt * 16 + (lane >> 2);
                int c = kb + (lane & 3);
                a[mt][0] = As[r][c];
                a[mt][1] = As[r + 8][c];
                a[mt][2] = As[r][c + 4];
                a[mt][3] = As[r + 8][c + 4];
            }
#pragma unroll
            for (int nt = 0; nt < 4; nt++) {
                int n = wn * 32 + nt * 8 + (lane >> 2);
                int c = kb + (lane & 3);
                float bg0 = Bg[n][c], bg1 = Bg[n][c + 4];
                float bu0 = Bu[n][c], bu1 = Bu[n][c + 4];
#pragma unroll
                for (int mt = 0; mt < 2; mt++) {
                    mma_tf32(cg[mt][nt], a[mt], bg0, bg1);
                    mma_tf32(cu[mt][nt], a[mt], bu0, bu1);
                }
            }
        }
        __syncthreads();
    }

    float* Hout = SHARED ? g_shidden : g_hidden;
#pragma unroll
    for (int mt = 0; mt < 2; mt++) {
#pragma unroll
        for (int nt = 0; nt < 4; nt++) {
            int rb = row0 + wm * 32 + mt * 16 + (lane >> 2);
            int nb = col0 + wn * 32 + nt * 8 + (lane & 3) * 2;
#pragma unroll
            for (int q = 0; q < 4; q++) {
                int rr = rb + ((q >= 2) ? 8 : 0);
                int nn = nb + (q & 1);
                float g = cg[mt][nt][q], u = cu[mt][nt][q];
                float s = 1.f / (1.f + __expf(-g));
                Hout[(size_t)rr * ID + nn] = g * s * u;
            }
        }
    }
}

// ---------------- GEMM2: hidden @ W_down ----------------
// BM=128, BN=128, BK=16, 256 threads (warps 4x2, warp tile 32x64)
template <bool SHARED>
__global__ __launch_bounds__(256) void gemm2_kernel(const float* __restrict__ wd,
                                                    float* __restrict__ out) {
    int tile = blockIdx.x;
    int row0, vrows;
    const float* B;
    if (SHARED) {
        row0 = tile * 128; vrows = 128; B = wd;
    } else {
        if (tile >= g_ntiles) return;
        row0 = g_tile_row0[tile];
        vrows = g_tile_rows[tile];
        B = wd + (size_t)g_tile_e[tile] * ID * HD;
    }
    const float* A = SHARED ? g_shidden : g_hidden;
    int col0 = blockIdx.y * 128;

    __shared__ float As[128][18];
    __shared__ float Bs[128][18];

    int tid = threadIdx.x, lane = tid & 31, warp = tid >> 5;
    int wm = warp >> 1, wn = warp & 1;

    float c[2][8][4];
#pragma unroll
    for (int i = 0; i < 2; i++)
#pragma unroll
        for (int j = 0; j < 8; j++)
#pragma unroll
            for (int q = 0; q < 4; q++) c[i][j][q] = 0.f;

    int ar = tid >> 1, ac = (tid & 1) * 8;
    int bk = tid >> 4, bn = (tid & 15) * 8;

    for (int k0 = 0; k0 < ID; k0 += 16) {
        const float* asrc = A + (size_t)(row0 + ar) * ID + k0 + ac;
        float4 a0 = *(const float4*)asrc;
        float4 a1 = *(const float4*)(asrc + 4);
        As[ar][ac + 0] = to_tf32(a0.x); As[ar][ac + 1] = to_tf32(a0.y);
        As[ar][ac + 2] = to_tf32(a0.z); As[ar][ac + 3] = to_tf32(a0.w);
        As[ar][ac + 4] = to_tf32(a1.x); As[ar][ac + 5] = to_tf32(a1.y);
        As[ar][ac + 6] = to_tf32(a1.z); As[ar][ac + 7] = to_tf32(a1.w);

        const float* bsrc = B + (size_t)(k0 + bk) * HD + col0 + bn;
        float4 b0 = *(const float4*)bsrc;
        float4 b1 = *(const float4*)(bsrc + 4);
        Bs[bn + 0][bk] = to_tf32(b0.x); Bs[bn + 1][bk] = to_tf32(b0.y);
        Bs[bn + 2][bk] = to_tf32(b0.z); Bs[bn + 3][bk] = to_tf32(b0.w);
        Bs[bn + 4][bk] = to_tf32(b1.x); Bs[bn + 5][bk] = to_tf32(b1.y);
        Bs[bn + 6][bk] = to_tf32(b1.z); Bs[bn + 7][bk] = to_tf32(b1.w);
        __syncthreads();

#pragma unroll
        for (int ks = 0; ks < 2; ks++) {
            int kb = ks * 8;
            float a[2][4];
#pragma unroll
            for (int mt = 0; mt < 2; mt++) {
                int r = wm * 32 + mt * 16 + (lane >> 2);
                int cc = kb + (lane & 3);
                a[mt][0] = As[r][cc];
                a[mt][1] = As[r + 8][cc];
                a[mt][2] = As[r][cc + 4];
                a[mt][3] = As[r + 8][cc + 4];
            }
#pragma unroll
            for (int nt = 0; nt < 8; nt++) {
                int n = wn * 64 + nt * 8 + (lane >> 2);
                int cc = kb + (lane & 3);
                float b0 = Bs[n][cc], b1 = Bs[n][cc + 4];
#pragma unroll
                for (int mt = 0; mt < 2; mt++) mma_tf32(c[mt][nt], a[mt], b0, b1);
            }
        }
        __syncthreads();
    }

#pragma unroll
    for (int mt = 0; mt < 2; mt++) {
#pragma unroll
        for (int nt = 0; nt < 8; nt++) {
            int lr0 = wm * 32 + mt * 16 + (lane >> 2);
            int nb  = col0 + wn * 64 + nt * 8 + (lane & 3) * 2;
#pragma unroll
            for (int q = 0; q < 4; q++) {
                int lr = lr0 + ((q >= 2) ? 8 : 0);
                int nn = nb + (q & 1);
                float v = c[mt][nt][q];
                if (SHARED) {
                    int t = row0 + lr;
                    out[(size_t)t * HD + nn] = g_gate[t] * v;
                } else {
                    if (lr < vrows) {
                        int t = g_row_token[row0 + lr];
                        atomicAdd(&out[(size_t)t * HD + nn], v);
                    }
                }
            }
        }
    }
}

// ---------------- launch ----------------
extern "C" void kernel_launch(void* const* d_in, const int* in_sizes, int n_in,
                              void* d_out, int out_size) {
    const float* x    = (const float*)d_in[0];
    const float* wr   = (const float*)d_in[1];
    const float* wgu  = (const float*)d_in[2];
    const float* wd   = (const float*)d_in[3];
    const float* wsgu = (const float*)d_in[4];
    const float* wsd  = (const float*)d_in[5];
    const float* wsg  = (const float*)d_in[6];
    float* out = (float*)d_out;

    init_kernel<<<1, 32>>>();
    router_kernel<<<T_TOK / 8, 256>>>(x, wr, wsg);
    scan_kernel<<<1, 1>>>();
    scatter_kernel<<<NA, 256>>>(x);

    // routed expert GEMM1 (+SwiGLU) over dynamic tiles
    gemm1_kernel<false><<<dim3(136, TWO_I / 2 / 64), 256>>>(nullptr, wgu);
    // shared expert GEMM1 (+SwiGLU)
    gemm1_kernel<true><<<dim3(T_TOK / 128, TWO_I / 2 / 64), 256>>>(x, wsgu);
    // shared expert GEMM2 writes gate*shared to every output element first
    gemm2_kernel<true><<<dim3(T_TOK / 128, HD / 128), 256>>>(wsd, out);
    // routed expert GEMM2 accumulates on top
    gemm2_kernel<false><<<dim3(136, HD / 128), 256>>>(wd, out);
}

// round 5
// speedup vs baseline: 1.8152x; 1.8152x over previous
#include <cuda_runtime.h>
#include <math.h>

#define T_TOK 8192
#define HD    2048
#define NE    8
#define ID    1408
#define TWO_I 2816
#define NA    16384
#define NA_PAD 17408   // 16384 + 8*128: per-expert regions aligned to 128 rows
#define MAX_TILES 144
#define RT_TILES 136   // fixed routed-tile grid slots; shared tiles start here

// ---------------- scratch (device globals; no allocation allowed) ----------------
__device__ float g_xin[(size_t)NA_PAD * HD];
__device__ float g_hidden[(size_t)NA_PAD * ID];
__device__ float g_shidden[(size_t)T_TOK * ID];
__device__ int   g_top_e[NA];
__device__ float g_top_p[NA];
__device__ float g_gate[T_TOK];
__device__ int   g_cnt[NE], g_off[NE], g_fill[NE];
__device__ int   g_row_token[NA_PAD];
__device__ int   g_tile_e[MAX_TILES], g_tile_row0[MAX_TILES], g_tile_rows[MAX_TILES];
__device__ int   g_ntiles;

// ---------------- helpers ----------------
__device__ __forceinline__ float to_tf32(float f) {
    unsigned u;
    asm("cvt.rna.tf32.f32 %0, %1;" : "=r"(u) : "f"(f));
    return __uint_as_float(u);
}

__device__ __forceinline__ void mma_tf32(float* c, const float* a, float b0, float b1) {
    asm volatile(
        "mma.sync.aligned.m16n8k8.row.col.f32.tf32.tf32.f32 "
        "{%0,%1,%2,%3}, {%4,%5,%6,%7}, {%8,%9}, {%0,%1,%2,%3};\n"
        : "+f"(c[0]), "+f"(c[1]), "+f"(c[2]), "+f"(c[3])
        : "r"(__float_as_uint(a[0])), "r"(__float_as_uint(a[1])),
          "r"(__float_as_uint(a[2])), "r"(__float_as_uint(a[3])),
          "r"(__float_as_uint(b0)),  "r"(__float_as_uint(b1)));
}

__device__ __forceinline__ void cp16(void* dst, const void* src) {
    unsigned d = (unsigned)__cvta_generic_to_shared(dst);
    asm volatile("cp.async.cg.shared.global [%0], [%1], 16;\n" :: "r"(d), "l"(src));
}
__device__ __forceinline__ void cp_commit() { asm volatile("cp.async.commit_group;\n"); }
__device__ __forceinline__ void cp_wait1()  { asm volatile("cp.async.wait_group 1;\n"); }

// ---------------- small kernels ----------------
__global__ void init_kernel() {
    int t = threadIdx.x;
    if (t < NE) { g_cnt[t] = 0; g_fill[t] = 0; }
}

__global__ void router_kernel(const float* __restrict__ x,
                              const float* __restrict__ wr,
                              const float* __restrict__ wsg) {
    int gw   = (blockIdx.x * blockDim.x + threadIdx.x) >> 5;
    int lane = threadIdx.x & 31;
    if (gw >= T_TOK) return;
    const float* xr = x + (size_t)gw * HD;
    float acc[NE];
#pragma unroll
    for (int e = 0; e < NE; e++) acc[e] = 0.f;
    float ag = 0.f;
    for (int h = lane; h < HD; h += 32) {
        float xv = xr[h];
        const float4* w = (const float4*)(wr + (size_t)h * NE);
        float4 w0 = w[0], w1 = w[1];
        acc[0] += xv * w0.x; acc[1] += xv * w0.y; acc[2] += xv * w0.z; acc[3] += xv * w0.w;
        acc[4] += xv * w1.x; acc[5] += xv * w1.y; acc[6] += xv * w1.z; acc[7] += xv * w1.w;
        ag += xv * wsg[h];
    }
#pragma unroll
    for (int o = 16; o > 0; o >>= 1) {
#pragma unroll
        for (int e = 0; e < NE; e++) acc[e] += __shfl_xor_sync(0xffffffffu, acc[e], o);
        ag += __shfl_xor_sync(0xffffffffu, ag, o);
    }
    if (lane == 0) {
        int i0 = 0; float v0 = acc[0];
#pragma unroll
        for (int e = 1; e < NE; e++) if (acc[e] > v0) { v0 = acc[e]; i0 = e; }
        int i1 = -1; float v1 = -1e30f;
#pragma unroll
        for (int e = 0; e < NE; e++) if (e != i0 && acc[e] > v1) { v1 = acc[e]; i1 = e; }
        float t  = __expf(v1 - v0);
        float p0 = 1.f / (1.f + t);
        float p1 = t  / (1.f + t);
        g_top_e[gw * 2]     = i0;
        g_top_e[gw * 2 + 1] = i1;
        g_top_p[gw * 2]     = p0;
        g_top_p[gw * 2 + 1] = p1;
        atomicAdd(&g_cnt[i0], 1);
        atomicAdd(&g_cnt[i1], 1);
        g_gate[gw] = 1.f / (1.f + __expf(-ag));
    }
}

// Expert regions aligned UP to 128 so no tile straddles two experts (R4 fix).
__global__ void scan_kernel() {
    if (threadIdx.x == 0 && blockIdx.x == 0) {
        int off = 0, nt = 0;
        for (int e = 0; e < NE; e++) {
            g_off[e] = off;
            int c = g_cnt[e];
            for (int r = 0; r < c; r += 128) {
                g_tile_e[nt]    = e;
                g_tile_row0[nt] = off + r;
                g_tile_rows[nt] = (c - r < 128) ? (c - r) : 128;
                nt++;
            }
            off = (off + c + 127) & ~127;
        }
        g_ntiles = nt;
    }
}

__global__ void scatter_kernel(const float* __restrict__ x) {
    int a = blockIdx.x;
    int t = a >> 1;
    __shared__ int srow;
    int   e = g_top_e[a];
    float p = g_top_p[a];
    if (threadIdx.x == 0) {
        int pos = atomicAdd(&g_fill[e], 1);
        int row = g_off[e] + pos;
        g_row_token[row] = t;
        srow = row;
    }
    __syncthreads();
    int row = srow;
    const float4* src = (const float4*)(x + (size_t)t * HD);
    float4*       dst = (float4*)(g_xin + (size_t)row * HD);
    for (int i = threadIdx.x; i < HD / 4; i += blockDim.x) {
        float4 v = src[i];
        v.x *= p; v.y *= p; v.z *= p; v.w *= p;
        dst[i] = v;
    }
}

// ---------------- GEMM1: X @ W_gate_up, fused SwiGLU, cp.async 2-stage ----------------
// BM=128, dual BN=64 (g/u), BK=16, 256 threads (warps 4x2). Routed + shared merged.
#define AS_STR 20
#define BG_STR 72
__global__ __launch_bounds__(256, 2) void gemm1_kernel(const float* __restrict__ xglob,
                                                       const float* __restrict__ wgu,
                                                       const float* __restrict__ wsgu) {
    int bx = blockIdx.x;
    bool sh = (bx >= RT_TILES);
    int row0;
    const float* A;
    const float* B;
    float* Hout;
    if (sh) {
        row0 = (bx - RT_TILES) * 128;
        A = xglob; B = wsgu; Hout = g_shidden;
    } else {
        if (bx >= g_ntiles) return;
        row0 = g_tile_row0[bx];
        A = g_xin;
        B = wgu + (size_t)g_tile_e[bx] * HD * TWO_I;
        Hout = g_hidden;
    }
    int col0 = blockIdx.y * 64;

    __shared__ float As[2][128][AS_STR];
    __shared__ float Bg[2][16][BG_STR];
    __shared__ float Bu[2][16][BG_STR];

    int tid = threadIdx.x, lane = tid & 31, warp = tid >> 5;
    int wm = warp >> 1, wn = warp & 1;

    float cg[2][4][4], cu[2][4][4];
#pragma unroll
    for (int i = 0; i < 2; i++)
#pragma unroll
        for (int j = 0; j < 4; j++)
#pragma unroll
            for (int q = 0; q < 4; q++) { cg[i][j][q] = 0.f; cu[i][j][q] = 0.f; }

    int ar = tid >> 1, ac = (tid & 1) * 8;      // A: 2 float4 per thread
    int bk = tid >> 4, bn = (tid & 15) * 4;     // B: 1 float4 per matrix per thread

    const float* a_base = A + (size_t)(row0 + ar) * HD + ac;

    // prologue: stage 0
    cp16(&As[0][ar][ac],     a_base);
    cp16(&As[0][ar][ac + 4], a_base + 4);
    {
        const float* bsrc = B + (size_t)bk * TWO_I + col0 + bn;
        cp16(&Bg[0][bk][bn], bsrc);
        cp16(&Bu[0][bk][bn], bsrc + ID);
    }
    cp_commit();

    const int NIT = HD / 16;
    for (int it = 0; it < NIT; it++) {
        int nxt = (it + 1) & 1, cur = it & 1;
        if (it + 1 < NIT) {
            int k0 = (it + 1) * 16;
            cp16(&As[nxt][ar][ac],     a_base + k0);
            cp16(&As[nxt][ar][ac + 4], a_base + k0 + 4);
            const float* bsrc = B + (size_t)(k0 + bk) * TWO_I + col0 + bn;
            cp16(&Bg[nxt][bk][bn], bsrc);
            cp16(&Bu[nxt][bk][bn], bsrc + ID);
        }
        cp_commit();
        cp_wait1();
        __syncthreads();

#pragma unroll
        for (int ks = 0; ks < 2; ks++) {
            int kb = ks * 8;
            float a[2][4];
#pragma unroll
            for (int mt = 0; mt < 2; mt++) {
                int r = wm * 32 + mt * 16 + (lane >> 2);
                int c = kb + (lane & 3);
                a[mt][0] = to_tf32(As[cur][r][c]);
                a[mt][1] = to_tf32(As[cur][r + 8][c]);
                a[mt][2] = to_tf32(As[cur][r][c + 4]);
                a[mt][3] = to_tf32(As[cur][r + 8][c + 4]);
            }
#pragma unroll
            for (int nt = 0; nt < 4; nt++) {
                int n = wn * 32 + nt * 8 + (lane >> 2);
                int c = kb + (lane & 3);
                float bg0 = to_tf32(Bg[cur][c][n]),     bg1 = to_tf32(Bg[cur][c + 4][n]);
                float bu0 = to_tf32(Bu[cur][c][n]),     bu1 = to_tf32(Bu[cur][c + 4][n]);
#pragma unroll
                for (int mt = 0; mt < 2; mt++) {
                    mma_tf32(cg[mt][nt], a[mt], bg0, bg1);
                    mma_tf32(cu[mt][nt], a[mt], bu0, bu1);
                }
            }
        }
        __syncthreads();
    }

#pragma unroll
    for (int mt = 0; mt < 2; mt++) {
#pragma unroll
        for (int nt = 0; nt < 4; nt++) {
            int rb = row0 + wm * 32 + mt * 16 + (lane >> 2);
            int nb = col0 + wn * 32 + nt * 8 + (lane & 3) * 2;
#pragma unroll
            for (int q = 0; q < 4; q++) {
                int rr = rb + ((q >= 2) ? 8 : 0);
                int nn = nb + (q & 1);
                float g = cg[mt][nt][q], u = cu[mt][nt][q];
                float s = 1.f / (1.f + __expf(-g));
                Hout[(size_t)rr * ID + nn] = g * s * u;
            }
        }
    }
}

// ---------------- GEMM2: hidden @ W_down, cp.async 2-stage, atomic epilogue ----------------
// BM=128, BN=128, BK=16, 256 threads. Routed + shared merged; out pre-zeroed.
#define BS_STR 136
__global__ __launch_bounds__(256, 2) void gemm2_kernel(const float* __restrict__ wd,
                                                       const float* __restrict__ wsd,
                                                       float* __restrict__ out) {
    int bx = blockIdx.x;
    bool sh = (bx >= RT_TILES);
    int row0, vrows;
    const float* A;
    const float* B;
    if (sh) {
        row0 = (bx - RT_TILES) * 128; vrows = 128;
        A = g_shidden; B = wsd;
    } else {
        if (bx >= g_ntiles) return;
        row0 = g_tile_row0[bx];
        vrows = g_tile_rows[bx];
        A = g_hidden;
        B = wd + (size_t)g_tile_e[bx] * ID * HD;
    }
    int col0 = blockIdx.y * 128;

    __shared__ float As[2][128][AS_STR];
    __shared__ float Bs[2][16][BS_STR];

    int tid = threadIdx.x, lane = tid & 31, warp = tid >> 5;
    int wm = warp >> 1, wn = warp & 1;

    float c[2][8][4];
#pragma unroll
    for (int i = 0; i < 2; i++)
#pragma unroll
        for (int j = 0; j < 8; j++)
#pragma unroll
            for (int q = 0; q < 4; q++) c[i][j][q] = 0.f;

    int ar = tid >> 1, ac = (tid & 1) * 8;
    int bk = tid >> 4, bn = (tid & 15) * 8;

    const float* a_base = A + (size_t)(row0 + ar) * ID + ac;

    cp16(&As[0][ar][ac],     a_base);
    cp16(&As[0][ar][ac + 4], a_base + 4);
    {
        const float* bsrc = B + (size_t)bk * HD + col0 + bn;
        cp16(&Bs[0][bk][bn],     bsrc);
        cp16(&Bs[0][bk][bn + 4], bsrc + 4);
    }
    cp_commit();

    const int NIT = ID / 16;
    for (int it = 0; it < NIT; it++) {
        int nxt = (it + 1) & 1, cur = it & 1;
        if (it + 1 < NIT) {
            int k0 = (it + 1) * 16;
            cp16(&As[nxt][ar][ac],     a_base + k0);
            cp16(&As[nxt][ar][ac + 4], a_base + k0 + 4);
            const float* bsrc = B + (size_t)(k0 + bk) * HD + col0 + bn;
            cp16(&Bs[nxt][bk][bn],     bsrc);
            cp16(&Bs[nxt][bk][bn + 4], bsrc + 4);
        }
        cp_commit();
        cp_wait1();
        __syncthreads();

#pragma unroll
        for (int ks = 0; ks < 2; ks++) {
            int kb = ks * 8;
            float a[2][4];
#pragma unroll
            for (int mt = 0; mt < 2; mt++) {
                int r = wm * 32 + mt * 16 + (lane >> 2);
                int cc = kb + (lane & 3);
                a[mt][0] = to_tf32(As[cur][r][cc]);
                a[mt][1] = to_tf32(As[cur][r + 8][cc]);
                a[mt][2] = to_tf32(As[cur][r][cc + 4]);
                a[mt][3] = to_tf32(As[cur][r + 8][cc + 4]);
            }
#pragma unroll
            for (int nt = 0; nt < 8; nt++) {
                int n = wn * 64 + nt * 8 + (lane >> 2);
                int cc = kb + (lane & 3);
                float b0 = to_tf32(Bs[cur][cc][n]);
                float b1 = to_tf32(Bs[cur][cc + 4][n]);
#pragma unroll
                for (int mt = 0; mt < 2; mt++) mma_tf32(c[mt][nt], a[mt], b0, b1);
            }
        }
        __syncthreads();
    }

#pragma unroll
    for (int mt = 0; mt < 2; mt++) {
#pragma unroll
        for (int nt = 0; nt < 8; nt++) {
            int lr0 = wm * 32 + mt * 16 + (lane >> 2);
            int nb  = col0 + wn * 64 + nt * 8 + (lane & 3) * 2;
#pragma unroll
            for (int q = 0; q < 4; q++) {
                int lr = lr0 + ((q >= 2) ? 8 : 0);
                int nn = nb + (q & 1);
                float v = c[mt][nt][q];
                if (lr < vrows) {
                    if (sh) {
                        int t = row0 + lr;
                        atomicAdd(&out[(size_t)t * HD + nn], g_gate[t] * v);
                    } else {
                        int t = g_row_token[row0 + lr];
                        atomicAdd(&out[(size_t)t * HD + nn], v);
                    }
                }
            }
        }
    }
}

// ---------------- launch ----------------
extern "C" void kernel_launch(void* const* d_in, const int* in_sizes, int n_in,
                              void* d_out, int out_size) {
    const float* x    = (const float*)d_in[0];
    const float* wr   = (const float*)d_in[1];
    const float* wgu  = (const float*)d_in[2];
    const float* wd   = (const float*)d_in[3];
    const float* wsgu = (const float*)d_in[4];
    const float* wsd  = (const float*)d_in[5];
    const float* wsg  = (const float*)d_in[6];
    float* out = (float*)d_out;

    init_kernel<<<1, 32>>>();
    router_kernel<<<T_TOK / 8, 256>>>(x, wr, wsg);
    scan_kernel<<<1, 1>>>();
    scatter_kernel<<<NA, 256>>>(x);
    cudaMemsetAsync(out, 0, (size_t)out_size * sizeof(float), 0);

    // GEMM1 (+SwiGLU): routed tiles [0,136) + shared tiles [136,200)
    gemm1_kernel<<<dim3(RT_TILES + T_TOK / 128, TWO_I / 2 / 64), 256>>>(x, wgu, wsgu);
    // GEMM2: both paths atomically accumulate into zeroed out
    gemm2_kernel<<<dim3(RT_TILES + T_TOK / 128, HD / 128), 256>>>(wd, wsd, out);
}